// round 3
// baseline (speedup 1.0000x reference)
#include <cuda_runtime.h>
#include <stdint.h>

#define NLAYERS 24
#define BATCH   512
#define RDIM    32
#define LQ      256
#define LOUT    257
#define NROWS   (NLAYERS*BATCH*RDIM)      /* 393216 rows */
#define NGROUPS (NROWS/4)                 /* 98304 groups of 4 rows */
#define NCHUNKS (NGROUPS/8)               /* 12288 chunks of 8 groups */
#define NCOMPUTE 64                       /* 64 blocks x 8 warps = 512 batches */
#define NCOPYB   3072                     /* 4 chunks per copy block */
#define FULLMASK 0xffffffffu

// ---------------- scratch (static device globals; no allocation) ----------------
__device__ float2 g_wT [NLAYERS*32*128];   // [l][j][row] -> (w_past, w_h)
__device__ float  g_f1T[NLAYERS*32*128];   // [l][j][k]

__device__ __forceinline__ float sigf(float v) { return 1.0f / (1.0f + __expf(-v)); }

// ---------------- K0: weight transposes for coalesced lane access ----------------
__global__ void prep_kernel(const float* __restrict__ conv_w,
                            const float* __restrict__ fc1_w) {
    int idx = blockIdx.x * blockDim.x + threadIdx.x;
    if (idx >= NLAYERS * 32 * 128) return;
    {
        // conv_w: [l][row(128)][j(32)][2]  (float2 index = (l*128+row)*32 + j)
        int l = idx / 4096, rem = idx & 4095, row = rem / 32, j = rem & 31;
        float2 v = ((const float2*)conv_w)[idx];
        g_wT[(l * 32 + j) * 128 + row] = v;
    }
    {
        // fc1_w: [k(128)][768];  dst [l][j][k], idx == (l*32+j)*128 + k
        int l = idx / 4096, rem = idx & 4095, j = rem >> 7, k = rem & 127;
        g_f1T[idx] = fc1_w[k * 768 + l * 32 + j];
    }
}

// ---------------- K1: fused recurrence + smem-staged queue copy ----------------
__global__ void __launch_bounds__(256, 4) main_kernel(
    const float* __restrict__ x,      const float* __restrict__ feat,
    const float* __restrict__ queues,
    const float* __restrict__ fc_h_w, const float* __restrict__ fc_h_b,
    const float* __restrict__ fc_c_w, const float* __restrict__ fc_c_b,
    const float* __restrict__ conv_b,
    const float* __restrict__ fc1_b,  const float* __restrict__ fc2_w,
    const float* __restrict__ fc2_b,
    float* __restrict__ out)
{
    __shared__ float s[8192];  // 8 groups x 4 rows x 256 floats = 32 KB

    if (blockIdx.x < NCOMPUTE) {
        // ---- compute path: 1 warp = 1 batch element; lane = R index ----
        int warp = threadIdx.x >> 5;
        int lane = threadIdx.x & 31;
        int b    = blockIdx.x * 8 + warp;

        float h, c;
        {
            float ha = fc_h_b[lane], ca = fc_c_b[lane];
            #pragma unroll
            for (int i = 0; i < 9; i++) {
                float wh = fc_h_w[lane * 9 + i];
                float wc = fc_c_w[lane * 9 + i];
                float v  = (i == 0) ? x[b] : feat[b * 8 + i - 1];
                ha += wh * v; ca += wc * v;
            }
            h = tanhf(ha); c = tanhf(ca);
        }
        // h BEFORE layer 0 -> t=256 column of layer 0's queue rows
        out[BATCH + (size_t)((0 * BATCH + b) * RDIM + lane) * LOUT + 256] = h;

        float y0 = 0.f, y1 = 0.f, y2 = 0.f, y3 = 0.f;

        #pragma unroll 1
        for (int l = 0; l < NLAYERS; l++) {
            int dil = 1 << (l & 7);
            float p = __ldg(queues + (size_t)((l * BATCH + b) * RDIM + lane) * LQ + (LQ - dil));

            float a0 = __ldg(conv_b + l * 128 +  0 + lane);
            float a1 = __ldg(conv_b + l * 128 + 32 + lane);
            float a2 = __ldg(conv_b + l * 128 + 64 + lane);
            float a3 = __ldg(conv_b + l * 128 + 96 + lane);

            const float2* wp = g_wT + l * 32 * 128;
            #pragma unroll 8
            for (int j = 0; j < 32; j++) {
                float pj = __shfl_sync(FULLMASK, p, j);
                float hj = __shfl_sync(FULLMASK, h, j);
                float2 w0 = wp[j * 128 +  0 + lane];
                float2 w1 = wp[j * 128 + 32 + lane];
                float2 w2 = wp[j * 128 + 64 + lane];
                float2 w3 = wp[j * 128 + 96 + lane];
                a0 += w0.x * pj + w0.y * hj;
                a1 += w1.x * pj + w1.y * hj;
                a2 += w2.x * pj + w2.y * hj;
                a3 += w3.x * pj + w3.y * hj;
            }
            c = sigf(a0) * c + tanhf(a1) * sigf(a2);
            h = sigf(a3) * tanhf(c);

            if (l < NLAYERS - 1)
                out[BATCH + (size_t)(((l + 1) * BATCH + b) * RDIM + lane) * LOUT + 256] = h;

            const float* f1p = g_f1T + l * 32 * 128;
            #pragma unroll 8
            for (int j = 0; j < 32; j++) {
                float hj = __shfl_sync(FULLMASK, h, j);
                y0 += f1p[j * 128 +  0 + lane] * hj;
                y1 += f1p[j * 128 + 32 + lane] * hj;
                y2 += f1p[j * 128 + 64 + lane] * hj;
                y3 += f1p[j * 128 + 96 + lane] * hj;
            }
        }

        float sacc = fmaxf(y0 + fc1_b[ 0 + lane], 0.f) * fc2_w[ 0 + lane]
                   + fmaxf(y1 + fc1_b[32 + lane], 0.f) * fc2_w[32 + lane]
                   + fmaxf(y2 + fc1_b[64 + lane], 0.f) * fc2_w[64 + lane]
                   + fmaxf(y3 + fc1_b[96 + lane], 0.f) * fc2_w[96 + lane];
        #pragma unroll
        for (int off = 16; off > 0; off >>= 1)
            sacc += __shfl_xor_sync(FULLMASK, sacc, off);
        if (lane == 0) out[b] = sacc + fc2_b[0];
    } else {
        // ---- copy path: dense LDG.128 -> smem -> dense STG.128 with 256->257 shift ----
        int tid = threadIdx.x;
        for (int chunk = blockIdx.x - NCOMPUTE; chunk < NCHUNKS; chunk += NCOPYB) {
            // Load: 8192 floats = 2048 float4, dense and aligned
            const float4* in4 = (const float4*)(queues + (size_t)chunk * 8192);
            float4* s4 = (float4*)s;
            #pragma unroll
            for (int k = 0; k < 8; k++)
                s4[k * 256 + tid] = __ldcs(in4 + k * 256 + tid);
            __syncthreads();

            // Store: 8 groups x 1028 floats = 8 x 257 float4, dense and aligned
            float* ob = out + BATCH + (size_t)chunk * 8224;
            int f = tid;                 // 0..255
            int e = 4 * f;
            int r = (e >= 257) + (e >= 514) + (e >= 771);
            int t = e - 257 * r;
            bool boundary = (f == 64) | (f == 128) | (f == 192);
            #pragma unroll
            for (int lg = 0; lg < 8; lg++) {
                const float* sp = s + lg * 1024 + r * 256 + t;
                float* op = ob + (size_t)lg * 1028 + e;
                if (boundary) {
                    // one element in e..e+3 is t==256 (owned by compute warps)
                    #pragma unroll
                    for (int j = 0; j < 4; j++) {
                        int ee = e + j;
                        int rr = (ee >= 257) + (ee >= 514) + (ee >= 771);
                        int tt = ee - 257 * rr;
                        if (tt < 256)
                            __stcs(op + j, s[lg * 1024 + rr * 256 + tt]);
                    }
                } else {
                    float4 v;
                    v.x = sp[0]; v.y = sp[1]; v.z = sp[2]; v.w = sp[3];
                    __stcs((float4*)op, v);
                }
            }
            // f == 256 tail: e=1024..1027 -> r=3, t=253,254,255,(256 skipped)
            if (tid < 8) {
                int lg = tid;
                float* op = ob + (size_t)lg * 1028 + 1024;
                const float* sp = s + lg * 1024 + 768 + 253;
                __stcs(op + 0, sp[0]);
                __stcs(op + 1, sp[1]);
                __stcs(op + 2, sp[2]);
            }
            __syncthreads();
        }
    }
}

extern "C" void kernel_launch(void* const* d_in, const int* in_sizes, int n_in,
                              void* d_out, int out_size) {
    const float* x      = (const float*)d_in[0];
    const float* feat   = (const float*)d_in[1];
    const float* queues = (const float*)d_in[2];
    const float* fc_h_w = (const float*)d_in[3];
    const float* fc_h_b = (const float*)d_in[4];
    const float* fc_c_w = (const float*)d_in[5];
    const float* fc_c_b = (const float*)d_in[6];
    const float* conv_w = (const float*)d_in[7];
    const float* conv_b = (const float*)d_in[8];
    const float* fc1_w  = (const float*)d_in[9];
    const float* fc1_b  = (const float*)d_in[10];
    const float* fc2_w  = (const float*)d_in[11];
    const float* fc2_b  = (const float*)d_in[12];
    float* out = (float*)d_out;

    prep_kernel<<<(NLAYERS * 32 * 128 + 255) / 256, 256>>>(conv_w, fc1_w);
    main_kernel<<<NCOMPUTE + NCOPYB, 256>>>(x, feat, queues,
                                            fc_h_w, fc_h_b, fc_c_w, fc_c_b,
                                            conv_b, fc1_b, fc2_w, fc2_b, out);
}